// round 7
// baseline (speedup 1.0000x reference)
#include <cuda_runtime.h>
#include <cuda_bf16.h>
#include <cstdint>

#define NUM_TAGS 32
#define START_TAG 30
#define STOP_TAG 31
#define MAX_B 1024
#define SEQ_S 512
#define LN2F 0.6931471805599453f

__device__ float g_partial[MAX_B];
__device__ unsigned g_done = 0;

__device__ __forceinline__ unsigned long long fma2(unsigned long long a,
                                                   unsigned long long b,
                                                   unsigned long long c) {
    unsigned long long d;
    asm("fma.rn.f32x2 %0, %1, %2, %3;" : "=l"(d) : "l"(a), "l"(b), "l"(c));
    return d;
}
__device__ __forceinline__ unsigned long long mul2(unsigned long long a,
                                                   unsigned long long b) {
    unsigned long long d;
    asm("mul.rn.f32x2 %0, %1, %2;" : "=l"(d) : "l"(a), "l"(b));
    return d;
}
__device__ __forceinline__ unsigned long long add2(unsigned long long a,
                                                   unsigned long long b) {
    unsigned long long d;
    asm("add.rn.f32x2 %0, %1, %2;" : "=l"(d) : "l"(a), "l"(b));
    return d;
}
__device__ __forceinline__ void unpack2(unsigned long long v, float& lo, float& hi) {
    asm("mov.b64 {%0, %1}, %2;" : "=f"(lo), "=f"(hi) : "l"(v));
}
__device__ __forceinline__ unsigned long long pack2(float lo, float hi) {
    unsigned long long v;
    asm("mov.b64 %0, {%1, %2};" : "=l"(v) : "f"(lo), "f"(hi));
    return v;
}
// Ordered same-warp smem ops; loop body is fully convergent (masks are
// warp-uniform selects), so no warp sync is needed between ST and LD.
__device__ __forceinline__ void sts32(uint32_t addr, float v) {
    asm volatile("st.shared.b32 [%0], %1;" :: "r"(addr), "f"(v) : "memory");
}
__device__ __forceinline__ ulonglong2 lds128(uint32_t addr) {
    ulonglong2 r;
    asm volatile("ld.shared.v2.b64 {%0, %1}, [%2];"
                 : "=l"(r.x), "=l"(r.y) : "r"(addr));
    return r;
}

// 4 warps/block; each warp runs TWO independent batch chains interleaved in
// its instruction stream to hide the per-step STS->LDS->fma dependence chain.
__global__ __launch_bounds__(128, 1) void crf_forward_kernel(
    const float* __restrict__ feats,       // [B, 512, 32]
    const int*   __restrict__ labels,      // [B, 512]
    const int*   __restrict__ lengths,     // [B]
    const float* __restrict__ transitions, // [32, 32]
    float* __restrict__ out, int B, int nblocks)
{
    __shared__ float sT[NUM_TAGS * NUM_TAGS];
    __shared__ float sAlpha[4][2][2][NUM_TAGS];  // [warp][chain][parity][tag]
    __shared__ float sred[128];
    __shared__ int sIsLast;

    const int tid  = threadIdx.x;
    const int w    = tid >> 5;
    const int lane = tid & 31;

    #pragma unroll
    for (int k = 0; k < 8; k++)
        sT[tid + k * 128] = transitions[tid + k * 128];
    __syncthreads();

    const int gw = blockIdx.x * 4 + w;       // global warp id
    const int nw = (B + 1) >> 1;             // number of dual-chain warps
    const int bA = gw;
    const int bB = gw + nw;
    const bool vA = (gw < nw);
    const bool vB = (bB < B);
    const bool active = vA || vB;            // warp-uniform

    if (active) {
        // Packed E columns: Epk[q] = ( exp(T[2q][lane]), exp(T[2q+1][lane]) )
        unsigned long long Epk[16];
        #pragma unroll
        for (int q = 0; q < 16; q++) {
            float e0 = __expf(sT[(2 * q) * NUM_TAGS + lane]);
            float e1 = __expf(sT[(2 * q + 1) * NUM_TAGS + lane]);
            Epk[q] = pack2(e0, e1);
        }

        const int lenA = vA ? lengths[bA] : 0;
        const int lenB = vB ? lengths[bB] : 0;
        const float* fbA = feats + (size_t)(vA ? bA : 0) * SEQ_S * NUM_TAGS;
        const float* fbB = feats + (size_t)(vB ? bB : 0) * SEQ_S * NUM_TAGS;
        const int maxlen = (lenA > lenB) ? lenA : lenB;

        const uint32_t aA0 = (uint32_t)__cvta_generic_to_shared(&sAlpha[w][0][0][0]);
        const uint32_t aA1 = (uint32_t)__cvta_generic_to_shared(&sAlpha[w][0][1][0]);
        const uint32_t aB0 = (uint32_t)__cvta_generic_to_shared(&sAlpha[w][1][0][0]);
        const uint32_t aB1 = (uint32_t)__cvta_generic_to_shared(&sAlpha[w][1][1][0]);
        const uint32_t wA0 = aA0 + lane * 4, wA1 = aA1 + lane * 4;
        const uint32_t wB0 = aB0 + lane * 4, wB1 = aB1 + lane * 4;

        // Prologue rows 1..7 and first superblock rows 8..15, per chain
        float fpreA[7], fpreB[7], fXA[8], fYA[8], fXB[8], fYB[8];
        #pragma unroll
        for (int d = 0; d < 7; d++) {
            fpreA[d] = fbA[(1 + d) * NUM_TAGS + lane];
            fpreB[d] = fbB[(1 + d) * NUM_TAGS + lane];
        }
        #pragma unroll
        for (int d = 0; d < 8; d++) {
            fXA[d] = fbA[(8 + d) * NUM_TAGS + lane];
            fXB[d] = fbB[(8 + d) * NUM_TAGS + lane];
        }

        float alphaA = __expf(fbA[lane] + sT[START_TAG * NUM_TAGS + lane]);
        float alphaB = __expf(fbB[lane] + sT[START_TAG * NUM_TAGS + lane]);
        int ilogA = 0, ilogB = 0;
        unsigned mbA = 127u << 23, mbB = 127u << 23;

// Shallow 8-accumulator tree: 8 mul2 + 8 fma2 + 7 add2.
#define CRF_STEP(ALPHA, WRA, RDA, EF, VALID)                                   \
    {                                                                          \
        sts32((WRA), ALPHA);                                                   \
        ulonglong2 q0 = lds128((RDA));       ulonglong2 q1 = lds128((RDA)+16); \
        ulonglong2 q2 = lds128((RDA)+32);    ulonglong2 q3 = lds128((RDA)+48); \
        ulonglong2 q4 = lds128((RDA)+64);    ulonglong2 q5 = lds128((RDA)+80); \
        ulonglong2 q6 = lds128((RDA)+96);    ulonglong2 q7 = lds128((RDA)+112);\
        unsigned long long c0 = mul2(q0.x, Epk[0]);                            \
        unsigned long long c1 = mul2(q0.y, Epk[1]);                            \
        unsigned long long c2 = mul2(q1.x, Epk[2]);                            \
        unsigned long long c3 = mul2(q1.y, Epk[3]);                            \
        unsigned long long c4 = mul2(q2.x, Epk[4]);                            \
        unsigned long long c5 = mul2(q2.y, Epk[5]);                            \
        unsigned long long c6 = mul2(q3.x, Epk[6]);                            \
        unsigned long long c7 = mul2(q3.y, Epk[7]);                            \
        c0 = fma2(q4.x, Epk[8],  c0);                                          \
        c1 = fma2(q4.y, Epk[9],  c1);                                          \
        c2 = fma2(q5.x, Epk[10], c2);                                          \
        c3 = fma2(q5.y, Epk[11], c3);                                          \
        c4 = fma2(q6.x, Epk[12], c4);                                          \
        c5 = fma2(q6.y, Epk[13], c5);                                          \
        c6 = fma2(q7.x, Epk[14], c6);                                          \
        c7 = fma2(q7.y, Epk[15], c7);                                          \
        c0 = add2(c0, c1); c2 = add2(c2, c3);                                  \
        c4 = add2(c4, c5); c6 = add2(c6, c7);                                  \
        c0 = add2(c0, c2); c4 = add2(c4, c6);                                  \
        c0 = add2(c0, c4);                                                     \
        float lo_, hi_; unpack2(c0, lo_, hi_);                                 \
        const float an_ = (lo_ + hi_) * (EF);                                  \
        ALPHA = (VALID) ? an_ : ALPHA;                                         \
    }

#define CRF_RENORM(ALPHA, MB, ILOG)                                            \
    {                                                                          \
        int e_ = (int)(((MB) >> 23) & 0xff);                                   \
        int sc_ = 254 - e_; sc_ = (sc_ < 1) ? 1 : sc_;                         \
        sc_ = (sc_ > 254) ? 254 : sc_;                                         \
        ALPHA *= __int_as_float(sc_ << 23);                                    \
        ILOG += 127 - sc_;                                                     \
        MB = __reduce_max_sync(0xffffffffu, __float_as_uint(ALPHA));           \
    }

// Dual-chain superblock: prefetch next 8 rows for both chains, run 8 steps
// of A and B interleaved, renorm both.
#define CRF_SUPER(CA, NA, CB, NB, TBASE)                                       \
    {                                                                          \
        _Pragma("unroll")                                                      \
        for (int u = 0; u < 8; u++) {                                          \
            int r_ = (TBASE) + 8 + u; r_ = (r_ < SEQ_S) ? r_ : (SEQ_S - 1);    \
            NA[u] = fbA[r_ * NUM_TAGS + lane];                                 \
            NB[u] = fbB[r_ * NUM_TAGS + lane];                                 \
        }                                                                      \
        _Pragma("unroll")                                                      \
        for (int u = 0; u < 8; u++) {                                          \
            const int t_ = (TBASE) + u;                                        \
            const float efA_ = __expf(CA[u]);                                  \
            const float efB_ = __expf(CB[u]);                                  \
            const uint32_t wra_ = (t_ & 1) ? wA1 : wA0;                        \
            const uint32_t rda_ = (t_ & 1) ? aA1 : aA0;                        \
            const uint32_t wrb_ = (t_ & 1) ? wB1 : wB0;                        \
            const uint32_t rdb_ = (t_ & 1) ? aB1 : aB0;                        \
            CRF_STEP(alphaA, wra_, rda_, efA_, t_ < lenA);                     \
            CRF_STEP(alphaB, wrb_, rdb_, efB_, t_ < lenB);                     \
        }                                                                      \
        CRF_RENORM(alphaA, mbA, ilogA);                                        \
        CRF_RENORM(alphaB, mbB, ilogB);                                        \
    }

        // Prologue: masked steps t = 1..7, both chains
        #pragma unroll
        for (int u = 0; u < 7; u++) {
            const int t_ = 1 + u;
            const float efA_ = __expf(fpreA[u]);
            const float efB_ = __expf(fpreB[u]);
            const uint32_t wra_ = (t_ & 1) ? wA1 : wA0;
            const uint32_t rda_ = (t_ & 1) ? aA1 : aA0;
            const uint32_t wrb_ = (t_ & 1) ? wB1 : wB0;
            const uint32_t rdb_ = (t_ & 1) ? aB1 : aB0;
            CRF_STEP(alphaA, wra_, rda_, efA_, t_ < lenA);
            CRF_STEP(alphaB, wrb_, rdb_, efB_, t_ < lenB);
        }
        CRF_RENORM(alphaA, mbA, ilogA);
        CRF_RENORM(alphaB, mbB, ilogB);

        // Main loop: ping-pong superblocks
        int t = 8;
        while (t < maxlen) {
            CRF_SUPER(fXA, fYA, fXB, fYB, t);
            t += 8;
            if (t >= maxlen) break;
            CRF_SUPER(fYA, fXA, fYB, fXB, t);
            t += 8;
        }
#undef CRF_STEP
#undef CRF_RENORM
#undef CRF_SUPER

        // Epilogues: gold score + final logsumexp per chain
        #pragma unroll 1
        for (int c = 0; c < 2; c++) {
            const bool vv = c ? vB : vA;
            if (!vv) continue;
            const int b_ = c ? bB : bA;
            const int len_ = c ? lenB : lenA;
            const float* fb_ = c ? fbB : fbA;
            const float alpha_ = c ? alphaB : alphaA;
            const int ilog_ = c ? ilogB : ilogA;
            const int labBase = b_ * SEQ_S;

            float epacc = 0.0f;
            for (int base = 0; base < len_; base += 32) {
                const int pos = base + lane;
                const bool v = pos < len_;
                const int cp = v ? pos : (len_ - 1);
                const int lab = labels[labBase + cp];
                const float fv = fb_[cp * NUM_TAGS + lab];
                float contrib = fv;
                if (pos >= 1) {
                    const int lp = labels[labBase + cp - 1];
                    contrib += sT[lp * NUM_TAGS + lab];
                }
                if (v) epacc += contrib;
            }

            float total = alpha_;
            #pragma unroll
            for (int off = 16; off >= 1; off >>= 1) {
                total += __shfl_xor_sync(0xffffffffu, total, off);
                epacc += __shfl_xor_sync(0xffffffffu, epacc, off);
            }
            const float fwd = __logf(total) + (float)ilog_ * LN2F;

            const int lab0 = labels[labBase];
            const int labL = labels[labBase + len_ - 1];
            const float gold = epacc + sT[START_TAG * NUM_TAGS + lab0]
                                     + sT[labL * NUM_TAGS + STOP_TAG];

            if (lane == 0) g_partial[b_] = fwd - gold;
        }
    }

    // Fused final reduction: last block to finish sums all partials.
    __syncthreads();
    if (tid == 0) {
        __threadfence();
        unsigned r = atomicAdd(&g_done, 1u);
        sIsLast = (r == (unsigned)(nblocks - 1));
    }
    __syncthreads();
    if (sIsLast) {
        __threadfence();
        float s = 0.0f;
        for (int i = tid; i < B; i += 128) s += g_partial[i];
        sred[tid] = s;
        __syncthreads();
        if (tid < 64) sred[tid] += sred[tid + 64];
        __syncthreads();
        if (tid < 32) {
            float v2 = sred[tid] + sred[tid + 32];
            #pragma unroll
            for (int off = 16; off >= 1; off >>= 1)
                v2 += __shfl_xor_sync(0xffffffffu, v2, off);
            if (tid == 0) {
                out[0] = v2 / (float)B;
                g_done = 0;   // reset for next graph replay
            }
        }
    }
}

extern "C" void kernel_launch(void* const* d_in, const int* in_sizes, int n_in,
                              void* d_out, int out_size)
{
    const float* feats       = (const float*)d_in[0];
    const int*   labels      = (const int*)d_in[1];
    const int*   lengths     = (const int*)d_in[2];
    const float* transitions = (const float*)d_in[3];
    float* out = (float*)d_out;

    const int B = in_sizes[2];
    const int nw = (B + 1) / 2;          // warps (2 chains each)
    const int blocks = (nw + 3) / 4;     // 4 warps per block

    crf_forward_kernel<<<blocks, 128>>>(feats, labels, lengths, transitions,
                                        out, B, blocks);
}

// round 8
// speedup vs baseline: 1.1436x; 1.1436x over previous
#include <cuda_runtime.h>
#include <cuda_bf16.h>
#include <cstdint>

#define NUM_TAGS 32
#define START_TAG 30
#define STOP_TAG 31
#define MAX_B 1024
#define SEQ_S 512
#define LN2F 0.6931471805599453f

__device__ float g_partial[MAX_B];
__device__ unsigned g_done = 0;

__device__ __forceinline__ unsigned long long fma2(unsigned long long a,
                                                   unsigned long long b,
                                                   unsigned long long c) {
    unsigned long long d;
    asm("fma.rn.f32x2 %0, %1, %2, %3;" : "=l"(d) : "l"(a), "l"(b), "l"(c));
    return d;
}
__device__ __forceinline__ unsigned long long mul2(unsigned long long a,
                                                   unsigned long long b) {
    unsigned long long d;
    asm("mul.rn.f32x2 %0, %1, %2;" : "=l"(d) : "l"(a), "l"(b));
    return d;
}
__device__ __forceinline__ unsigned long long add2(unsigned long long a,
                                                   unsigned long long b) {
    unsigned long long d;
    asm("add.rn.f32x2 %0, %1, %2;" : "=l"(d) : "l"(a), "l"(b));
    return d;
}
__device__ __forceinline__ void unpack2(unsigned long long v, float& lo, float& hi) {
    asm("mov.b64 {%0, %1}, %2;" : "=f"(lo), "=f"(hi) : "l"(v));
}
__device__ __forceinline__ unsigned long long pack2(float lo, float hi) {
    unsigned long long v;
    asm("mov.b64 %0, {%1, %2};" : "=l"(v) : "f"(lo), "f"(hi));
    return v;
}
// Same-warp smem ops execute in issue order at the LSU; body is convergent.
__device__ __forceinline__ void sts32(uint32_t addr, float v) {
    asm volatile("st.shared.b32 [%0], %1;" :: "r"(addr), "f"(v) : "memory");
}
__device__ __forceinline__ ulonglong2 lds128(uint32_t addr) {
    ulonglong2 r;
    asm volatile("ld.shared.v2.b64 {%0, %1}, [%2];"
                 : "=l"(r.x), "=l"(r.y) : "r"(addr));
    return r;
}

// 4 warps/block spread across SMSPs; ONE chain per warp; minimal-latency step.
__global__ __launch_bounds__(128, 1) void crf_forward_kernel(
    const float* __restrict__ feats,       // [B, 512, 32]
    const int*   __restrict__ labels,      // [B, 512]
    const int*   __restrict__ lengths,     // [B]
    const float* __restrict__ transitions, // [32, 32]
    float* __restrict__ out, int B, int nblocks)
{
    __shared__ float sT[NUM_TAGS * NUM_TAGS];
    __shared__ float sAlpha[4][NUM_TAGS];     // [warp][tag], single buffer
    __shared__ float sred[128];
    __shared__ int sIsLast;

    const int tid  = threadIdx.x;
    const int w    = tid >> 5;
    const int lane = tid & 31;

    #pragma unroll
    for (int k = 0; k < 8; k++)
        sT[tid + k * 128] = transitions[tid + k * 128];
    __syncthreads();

    const int b = blockIdx.x * 4 + w;

    if (b < B) {
        // Packed E columns: Epk[q] = ( exp(T[2q][lane]), exp(T[2q+1][lane]) )
        unsigned long long Epk[16];
        #pragma unroll
        for (int q = 0; q < 16; q++) {
            float e0 = __expf(sT[(2 * q) * NUM_TAGS + lane]);
            float e1 = __expf(sT[(2 * q + 1) * NUM_TAGS + lane]);
            Epk[q] = pack2(e0, e1);
        }

        const int len = lengths[b];
        const float* fb = feats + (size_t)b * SEQ_S * NUM_TAGS;
        const int labBase = b * SEQ_S;

        const uint32_t abase = (uint32_t)__cvta_generic_to_shared(&sAlpha[w][0]);
        const uint32_t wraddr = abase + lane * 4;

        // Prologue rows 1..7 and first superblock rows 8..15
        float fpre[7], fX[8], fY[8];
        #pragma unroll
        for (int d = 0; d < 7; d++) fpre[d] = fb[(1 + d) * NUM_TAGS + lane];
        #pragma unroll
        for (int d = 0; d < 8; d++) fX[d] = fb[(8 + d) * NUM_TAGS + lane];

        float alpha = __expf(fb[lane] + sT[START_TAG * NUM_TAGS + lane]);
        int ilog = 0;
        unsigned prev_mb = 127u << 23;

// Minimal-latency step: 8 mul2 + 8 fma2 + skewed add tree (late loads shallow).
// MASKED=0 -> no select on the chain.
#define CRF_STEP_CORE(EF)                                                      \
        sts32(wraddr, alpha);                                                  \
        ulonglong2 q0 = lds128(abase);       ulonglong2 q1 = lds128(abase+16); \
        ulonglong2 q2 = lds128(abase+32);    ulonglong2 q3 = lds128(abase+48); \
        ulonglong2 q4 = lds128(abase+64);    ulonglong2 q5 = lds128(abase+80); \
        ulonglong2 q6 = lds128(abase+96);    ulonglong2 q7 = lds128(abase+112);\
        unsigned long long c0 = mul2(q0.x, Epk[0]);                            \
        unsigned long long c1 = mul2(q0.y, Epk[1]);                            \
        unsigned long long c2 = mul2(q1.x, Epk[2]);                            \
        unsigned long long c3 = mul2(q1.y, Epk[3]);                            \
        c0 = fma2(q2.x, Epk[4],  c0);                                          \
        c1 = fma2(q2.y, Epk[5],  c1);                                          \
        c2 = fma2(q3.x, Epk[6],  c2);                                          \
        c3 = fma2(q3.y, Epk[7],  c3);                                          \
        /* early partial tree on first half */                                 \
        unsigned long long p0 = add2(c0, c1);                                  \
        unsigned long long p1 = add2(c2, c3);                                  \
        unsigned long long s0 = add2(p0, p1);                                  \
        /* second half: later loads, shallower combine */                      \
        unsigned long long d0 = mul2(q4.x, Epk[8]);                            \
        unsigned long long d1 = mul2(q4.y, Epk[9]);                            \
        unsigned long long d2 = mul2(q5.x, Epk[10]);                           \
        unsigned long long d3 = mul2(q5.y, Epk[11]);                           \
        d0 = fma2(q6.x, Epk[12], d0);                                          \
        d1 = fma2(q6.y, Epk[13], d1);                                          \
        d2 = fma2(q7.x, Epk[14], d2);                                          \
        d3 = fma2(q7.y, Epk[15], d3);                                          \
        unsigned long long p2 = add2(d0, d1);                                  \
        unsigned long long p3 = add2(d2, d3);                                  \
        unsigned long long s1 = add2(p2, p3);                                  \
        unsigned long long ss = add2(s0, s1);                                  \
        float lo_, hi_; unpack2(ss, lo_, hi_);                                 \
        const float an_ = (lo_ + hi_) * (EF);

#define CRF_STEP(EF)        { CRF_STEP_CORE(EF) alpha = an_; }
#define CRF_STEP_MASK(EF,V) { CRF_STEP_CORE(EF) alpha = (V) ? an_ : alpha; }

#define CRF_RENORM                                                             \
    {                                                                          \
        int e_ = (int)((prev_mb >> 23) & 0xff);                                \
        int sc_ = 254 - e_; sc_ = (sc_ < 1) ? 1 : sc_;                         \
        sc_ = (sc_ > 254) ? 254 : sc_;                                         \
        alpha *= __int_as_float(sc_ << 23);                                    \
        ilog += 127 - sc_;                                                     \
        prev_mb = __reduce_max_sync(0xffffffffu, __float_as_uint(alpha));      \
    }

// Unmasked superblock (requires TBASE+8 <= len): prefetch next 8 rows, 8 steps.
#define CRF_SUPER(CUR, NXT, TBASE)                                             \
    {                                                                          \
        _Pragma("unroll")                                                      \
        for (int u = 0; u < 8; u++) {                                          \
            int r_ = (TBASE) + 8 + u; r_ = (r_ < SEQ_S) ? r_ : (SEQ_S - 1);    \
            NXT[u] = fb[r_ * NUM_TAGS + lane];                                 \
        }                                                                      \
        float ef_[8];                                                          \
        _Pragma("unroll")                                                      \
        for (int u = 0; u < 8; u++) ef_[u] = __expf(CUR[u]);                   \
        _Pragma("unroll")                                                      \
        for (int u = 0; u < 8; u++) { CRF_STEP(ef_[u]); }                      \
        CRF_RENORM;                                                            \
    }

        // Prologue: masked steps t = 1..7
        #pragma unroll
        for (int u = 0; u < 7; u++) {
            const int t_ = 1 + u;
            const float ef_ = __expf(fpre[u]);
            CRF_STEP_MASK(ef_, t_ < len);
        }
        CRF_RENORM;

        // Main loop: unmasked ping-pong superblocks while fully in range
        int t = 8;
        while (t + 8 <= len) {
            CRF_SUPER(fX, fY, t);
            t += 8;
            if (t + 8 > len) { 
                #pragma unroll
                for (int u = 0; u < 8; u++) fX[u] = fY[u];
                break;
            }
            CRF_SUPER(fY, fX, t);
            t += 8;
        }
        // Tail: up to 7 masked steps from fX
        #pragma unroll
        for (int u = 0; u < 7; u++) {
            const int t_ = t + u;
            const float ef_ = __expf(fX[u]);
            CRF_STEP_MASK(ef_, t_ < len);
        }
#undef CRF_STEP_CORE
#undef CRF_STEP
#undef CRF_STEP_MASK
#undef CRF_RENORM
#undef CRF_SUPER

        // Gold score epilogue (order-independent, latency tolerant)
        float epacc = 0.0f;
        for (int base = 0; base < len; base += 32) {
            const int pos = base + lane;
            const bool v = pos < len;
            const int cp = v ? pos : (len - 1);
            const int lab = labels[labBase + cp];
            const float fv = fb[cp * NUM_TAGS + lab];
            float contrib = fv;
            if (pos >= 1) {
                const int lp = labels[labBase + cp - 1];
                contrib += sT[lp * NUM_TAGS + lab];
            }
            if (v) epacc += contrib;
        }

        float total = alpha;
        #pragma unroll
        for (int off = 16; off >= 1; off >>= 1) {
            total += __shfl_xor_sync(0xffffffffu, total, off);
            epacc += __shfl_xor_sync(0xffffffffu, epacc, off);
        }
        const float fwd = __logf(total) + (float)ilog * LN2F;

        const int lab0 = labels[labBase];
        const int labL = labels[labBase + len - 1];
        const float gold = epacc + sT[START_TAG * NUM_TAGS + lab0]
                                 + sT[labL * NUM_TAGS + STOP_TAG];

        if (lane == 0) g_partial[b] = fwd - gold;
    }

    // Fused final reduction: last block to finish sums all partials.
    __syncthreads();
    if (tid == 0) {
        __threadfence();
        unsigned r = atomicAdd(&g_done, 1u);
        sIsLast = (r == (unsigned)(nblocks - 1));
    }
    __syncthreads();
    if (sIsLast) {
        __threadfence();
        float s = 0.0f;
        for (int i = tid; i < B; i += 128) s += g_partial[i];
        sred[tid] = s;
        __syncthreads();
        if (tid < 64) sred[tid] += sred[tid + 64];
        __syncthreads();
        if (tid < 32) {
            float v2 = sred[tid] + sred[tid + 32];
            #pragma unroll
            for (int off = 16; off >= 1; off >>= 1)
                v2 += __shfl_xor_sync(0xffffffffu, v2, off);
            if (tid == 0) {
                out[0] = v2 / (float)B;
                g_done = 0;   // reset for next graph replay
            }
        }
    }
}

extern "C" void kernel_launch(void* const* d_in, const int* in_sizes, int n_in,
                              void* d_out, int out_size)
{
    const float* feats       = (const float*)d_in[0];
    const int*   labels      = (const int*)d_in[1];
    const int*   lengths     = (const int*)d_in[2];
    const float* transitions = (const float*)d_in[3];
    float* out = (float*)d_out;

    const int B = in_sizes[2];
    const int blocks = (B + 3) / 4;   // 4 warps/block, one chain per warp

    crf_forward_kernel<<<blocks, 128>>>(feats, labels, lengths, transitions,
                                        out, B, blocks);
}